// round 6
// baseline (speedup 1.0000x reference)
#include <cuda_runtime.h>
#include <cstdint>

// ---------------- static device scratch ----------------
#define MAXN 131072
#define MAXE 2000000

__device__ int    g_detect;                 // 1 => int32 edges, 0 => int64
__device__ int    g_deg[MAXN];
__device__ float  g_dinv[MAXN];
__device__ float  g_dinv2[MAXN];
__device__ int    g_offs[MAXN + 1];
__device__ int    g_cursor[MAXN];
__device__ int    g_bsum[MAXN / 256 + 2];
__device__ int2   g_csr[MAXE];              // (src, norm-as-int)
__device__ float  g_bufA[(size_t)MAXN * 96];
__device__ float  g_bufB[(size_t)MAXN * 96];
__device__ double g_sumS[3][8][96];
__device__ double g_sqS[3][8][96];

// ---------------- grid barrier ----------------
__device__ unsigned g_cnt;
__device__ volatile unsigned g_gen;

__device__ __forceinline__ void gsync(int nb) {
    __syncthreads();
    if (threadIdx.x == 0) {
        __threadfence();
        unsigned gen = g_gen;
        if (atomicAdd(&g_cnt, 1u) == (unsigned)(nb - 1)) {
            atomicExch(&g_cnt, 0u);
            __threadfence();
            g_gen = gen + 1;
        } else {
            while (g_gen == gen) __nanosleep(64);
        }
        __threadfence();
    }
    __syncthreads();
}

// ---------------- phase helpers ----------------

// CSR gather: warp per node, NL float4 lanes active
template<int NL>
__device__ __forceinline__ void agg_phase(const float* __restrict__ h,
                                          float* __restrict__ outp, int N, int nb) {
    int lane = threadIdx.x & 31;
    int w0   = blockIdx.x * 8 + (threadIdx.x >> 5);
    int totW = nb * 8;
    const float4* hp = (const float4*)h;
    bool act = lane < NL;
    for (int gw = w0; gw < N; gw += totW) {
        float4 acc = make_float4(0, 0, 0, 0);
        if (act) {
            float4 v = __ldg(hp + (size_t)gw * NL + lane);
            float w = g_dinv2[gw];
            acc = make_float4(v.x * w, v.y * w, v.z * w, v.w * w);
        }
        int beg = g_offs[gw], end = g_offs[gw + 1];
        for (int e0 = beg; e0 < end; e0 += 32) {
            int e = e0 + lane;
            int2 ed = (e < end) ? g_csr[e] : make_int2(0, 0);
            int m = end - e0; if (m > 32) m = 32;
            int j = 0;
            for (; j + 2 <= m; j += 2) {
                int   s0 = __shfl_sync(0xffffffffu, ed.x, j);
                float n0 = __int_as_float(__shfl_sync(0xffffffffu, ed.y, j));
                int   s1 = __shfl_sync(0xffffffffu, ed.x, j + 1);
                float n1 = __int_as_float(__shfl_sync(0xffffffffu, ed.y, j + 1));
                if (act) {
                    float4 v0 = __ldg(hp + (size_t)s0 * NL + lane);
                    float4 v1 = __ldg(hp + (size_t)s1 * NL + lane);
                    acc.x = fmaf(n0, v0.x, acc.x); acc.y = fmaf(n0, v0.y, acc.y);
                    acc.z = fmaf(n0, v0.z, acc.z); acc.w = fmaf(n0, v0.w, acc.w);
                    acc.x = fmaf(n1, v1.x, acc.x); acc.y = fmaf(n1, v1.y, acc.y);
                    acc.z = fmaf(n1, v1.z, acc.z); acc.w = fmaf(n1, v1.w, acc.w);
                }
            }
            if (j < m) {
                int   s0 = __shfl_sync(0xffffffffu, ed.x, j);
                float n0 = __int_as_float(__shfl_sync(0xffffffffu, ed.y, j));
                if (act) {
                    float4 v0 = __ldg(hp + (size_t)s0 * NL + lane);
                    acc.x = fmaf(n0, v0.x, acc.x); acc.y = fmaf(n0, v0.y, acc.y);
                    acc.z = fmaf(n0, v0.z, acc.z); acc.w = fmaf(n0, v0.w, acc.w);
                }
            }
        }
        if (act) ((float4*)outp)[(size_t)gw * NL + lane] = acc;
    }
}

// GEMM Y[N,96] = X[N,Fi] @ W + b with FFMA2, stats accumulated across tiles
__device__ __forceinline__ void gemm_phase(
    const float* __restrict__ X, const float* __restrict__ W,
    const float* __restrict__ b, float* __restrict__ Y,
    int N, int Fi, int layer, float* Ws, float* Xt, int nb) {
    int tid = threadIdx.x;
    int tx = tid & 15, ty = tid >> 4;
    for (int i = tid; i < Fi * 96; i += 256) Ws[i] = W[i];
    int cb = ty * 6;
    float bb[6];
    #pragma unroll
    for (int j = 0; j < 6; j++) bb[j] = b[cb + j];
    float ls[6] = {0, 0, 0, 0, 0, 0}, lq[6] = {0, 0, 0, 0, 0, 0};

    int nT = (N + 31) >> 5;
    for (int tile = blockIdx.x; tile < nT; tile += nb) {
        int row0 = tile * 32;
        __syncthreads();
        for (int i = tid; i < 32 * Fi; i += 256) {
            int r = i & 31, k = i >> 5;
            int row = row0 + r;
            Xt[k * 32 + r] = (row < N) ? X[(size_t)row * Fi + k] : 0.0f;
        }
        __syncthreads();

        unsigned long long acc[2][3] = {{0, 0, 0}, {0, 0, 0}};
        #pragma unroll 4
        for (int k = 0; k < Fi; k++) {
            float2 a2 = *(const float2*)&Xt[k * 32 + 2 * tx];
            unsigned long long p0, p1;
            asm("mov.b64 %0, {%1, %1};" : "=l"(p0) : "f"(a2.x));
            asm("mov.b64 %0, {%1, %1};" : "=l"(p1) : "f"(a2.y));
            const unsigned long long* wrow = (const unsigned long long*)&Ws[k * 96 + cb];
            #pragma unroll
            for (int p = 0; p < 3; p++) {
                unsigned long long w2 = wrow[p];
                asm("fma.rn.f32x2 %0, %1, %2, %0;" : "+l"(acc[0][p]) : "l"(p0), "l"(w2));
                asm("fma.rn.f32x2 %0, %1, %2, %0;" : "+l"(acc[1][p]) : "l"(p1), "l"(w2));
            }
        }
        #pragma unroll
        for (int rr = 0; rr < 2; rr++) {
            int row = row0 + 2 * tx + rr;
            if (row < N) {
                float v[6];
                #pragma unroll
                for (int p = 0; p < 3; p++)
                    asm("mov.b64 {%0, %1}, %2;" : "=f"(v[2*p]), "=f"(v[2*p+1]) : "l"(acc[rr][p]));
                #pragma unroll
                for (int j = 0; j < 6; j++) {
                    float val = v[j] + bb[j];
                    v[j] = val;
                    ls[j] += val; lq[j] += val * val;
                }
                float2* yp = (float2*)&Y[(size_t)row * 96 + cb];
                yp[0] = make_float2(v[0], v[1]);
                yp[1] = make_float2(v[2], v[3]);
                yp[2] = make_float2(v[4], v[5]);
            }
        }
    }

    // one stats reduction per block (Xt reused; pad 102)
    __syncthreads();
    float* sr = Xt;
    int sh = blockIdx.x & 7;
    #pragma unroll
    for (int j = 0; j < 6; j++) sr[tx * 102 + cb + j] = ls[j];
    __syncthreads();
    for (int st = 8; st; st >>= 1) {
        if (tx < st)
            #pragma unroll
            for (int j = 0; j < 6; j++)
                sr[tx * 102 + cb + j] += sr[(tx + st) * 102 + cb + j];
        __syncthreads();
    }
    if (tx == 0)
        #pragma unroll
        for (int j = 0; j < 6; j++) atomicAdd(&g_sumS[layer][sh][cb + j], (double)sr[cb + j]);
    __syncthreads();
    #pragma unroll
    for (int j = 0; j < 6; j++) sr[tx * 102 + cb + j] = lq[j];
    __syncthreads();
    for (int st = 8; st; st >>= 1) {
        if (tx < st)
            #pragma unroll
            for (int j = 0; j < 6; j++)
                sr[tx * 102 + cb + j] += sr[(tx + st) * 102 + cb + j];
        __syncthreads();
    }
    if (tx == 0)
        #pragma unroll
        for (int j = 0; j < 6; j++) atomicAdd(&g_sqS[layer][sh][cb + j], (double)sr[cb + j]);
}

// compute BN coefficients into smem (per block, redundant but cheap)
__device__ __forceinline__ void bn_coeffs(int layer, const float* __restrict__ g,
                                          const float* __restrict__ be, int N,
                                          float* sc, float* sf) {
    int t = threadIdx.x;
    if (t < 96) {
        double s = 0.0, q = 0.0;
        #pragma unroll
        for (int i = 0; i < 8; i++) { s += g_sumS[layer][i][t]; q += g_sqS[layer][i][t]; }
        double mu  = s / (double)N;
        double var = q / (double)N - mu * mu;
        if (var < 0.0) var = 0.0;
        float a = g[t] * rsqrtf((float)var + 1e-5f);
        sc[t] = a;
        sf[t] = be[t] - (float)mu * a;
    }
    __syncthreads();
}

// elementwise BN+ReLU in place (fp32)
__device__ __forceinline__ void bnrelu_phase(float* __restrict__ X, int N,
                                             const float* sc, const float* sf, int nb) {
    int total4 = N * 24;
    for (int i = blockIdx.x * 256 + threadIdx.x; i < total4; i += nb * 256) {
        int c = (i % 24) * 4;
        float4 v = ((const float4*)X)[i];
        v.x = fmaxf(fmaf(v.x, sc[c],     sf[c]),     0.f);
        v.y = fmaxf(fmaf(v.y, sc[c + 1], sf[c + 1]), 0.f);
        v.z = fmaxf(fmaf(v.z, sc[c + 2], sf[c + 2]), 0.f);
        v.w = fmaxf(fmaf(v.w, sc[c + 3], sf[c + 3]), 0.f);
        ((float4*)X)[i] = v;
    }
}

// ---------------- the megakernel ----------------
__global__ __launch_bounds__(256) void k_mega(
    const float* __restrict__ x, const int* __restrict__ ei,
    const float* __restrict__ W1, const float* __restrict__ b1,
    const float* __restrict__ g1, const float* __restrict__ be1,
    const float* __restrict__ W2, const float* __restrict__ b2,
    const float* __restrict__ g2, const float* __restrict__ be2,
    const float* __restrict__ W3, const float* __restrict__ b3,
    const float* __restrict__ g3, const float* __restrict__ be3,
    const float* __restrict__ W4, const float* __restrict__ b4,
    float* __restrict__ out, int N, int E, int Fin, int nb)
{
    __shared__ __align__(16) char sp[49152];
    float* Ws = (float*)sp;              // 9216 floats
    float* Xt = (float*)sp + 9216;       // 3072 floats
    int tid = threadIdx.x;
    int bid = blockIdx.x;

    // ---- P0: zero deg + stats, detect edge dtype ----
    for (int i = bid * 256 + tid; i < N; i += nb * 256) g_deg[i] = 0;
    for (int i = bid * 256 + tid; i < 2304; i += nb * 256) {
        ((double*)g_sumS)[i] = 0.0;
        ((double*)g_sqS)[i]  = 0.0;
    }
    if (bid == 0) {
        if (tid == 0) g_detect = 0;
        __syncthreads();
        if (ei[2 * tid + 1] != 0) g_detect = 1;   // benign race, all write 1
    }
    gsync(nb);
    int is64 = (g_detect == 0);

    // ---- P1: count degrees ----
    for (int e = bid * 256 + tid; e < E; e += nb * 256) {
        int d = is64 ? ei[2 * (E + e)] : ei[E + e];
        atomicAdd(&g_deg[d], 1);
    }
    gsync(nb);

    // ---- P2: dinv + per-chunk degree sums ----
    int nch = (N + 255) >> 8;
    int* ish = (int*)sp;
    int* red = (int*)sp + 256;
    for (int c = bid; c < nch; c += nb) {
        int i = c * 256 + tid;
        int dg = (i < N) ? g_deg[i] : 0;
        if (i < N) {
            float dt = (float)(dg + 1);   // +1 self-loop
            g_dinv[i]  = rsqrtf(dt);
            g_dinv2[i] = 1.0f / dt;
        }
        __syncthreads();
        ish[tid] = dg;
        __syncthreads();
        for (int s = 128; s; s >>= 1) { if (tid < s) ish[tid] += ish[tid + s]; __syncthreads(); }
        if (tid == 0) g_bsum[c] = ish[0];
        __syncthreads();
    }
    gsync(nb);

    // ---- P3: offsets (chunk scan + inlined cross-chunk prefix) ----
    for (int c = bid; c < nch; c += nb) {
        int acc = 0;
        for (int i = tid; i < c; i += 256) acc += g_bsum[i];
        __syncthreads();
        red[tid] = acc;
        __syncthreads();
        for (int s = 128; s; s >>= 1) { if (tid < s) red[tid] += red[tid + s]; __syncthreads(); }
        int bpre = red[0];
        int i = c * 256 + tid;
        int v = (i < N) ? g_deg[i] : 0;
        __syncthreads();
        ish[tid] = v;
        __syncthreads();
        for (int o = 1; o < 256; o <<= 1) {
            int xv = (tid >= o) ? ish[tid - o] : 0;
            __syncthreads();
            ish[tid] += xv;
            __syncthreads();
        }
        if (i < N) {
            int off = bpre + ish[tid] - v;
            g_offs[i]   = off;
            g_cursor[i] = off;
            if (i == N - 1) g_offs[N] = off + v;
        }
        __syncthreads();
    }
    gsync(nb);

    // ---- P4: scatter edges into CSR ----
    for (int e = bid * 256 + tid; e < E; e += nb * 256) {
        int s, d;
        if (is64) { s = ei[2 * e]; d = ei[2 * (E + e)]; }
        else      { s = ei[e];     d = ei[E + e]; }
        int pos = atomicAdd(&g_cursor[d], 1);
        g_csr[pos] = make_int2(s, __float_as_int(g_dinv[s] * g_dinv[d]));
    }
    gsync(nb);

    // ---- layer 1 ----
    agg_phase<8>(x, g_bufA, N, nb);
    gsync(nb);
    gemm_phase(g_bufA, W1, b1, g_bufB, N, Fin, 0, Ws, Xt, nb);
    gsync(nb);
    {
        float* sc = (float*)sp; float* sf = (float*)sp + 96;
        bn_coeffs(0, g1, be1, N, sc, sf);
        bnrelu_phase(g_bufB, N, sc, sf, nb);
    }
    gsync(nb);

    // ---- layer 2 ----
    agg_phase<24>(g_bufB, g_bufA, N, nb);
    gsync(nb);
    gemm_phase(g_bufA, W2, b2, g_bufB, N, 96, 1, Ws, Xt, nb);
    gsync(nb);
    {
        float* sc = (float*)sp; float* sf = (float*)sp + 96;
        bn_coeffs(1, g2, be2, N, sc, sf);
        bnrelu_phase(g_bufB, N, sc, sf, nb);
    }
    gsync(nb);

    // ---- layer 3 ----
    agg_phase<24>(g_bufB, g_bufA, N, nb);
    gsync(nb);
    gemm_phase(g_bufA, W3, b3, g_bufB, N, 96, 2, Ws, Xt, nb);
    gsync(nb);

    // ---- layer 4: BN3+ReLU fused into projection -> T (in bufA) ----
    {
        float* sc = (float*)sp; float* sf = (float*)sp + 96;
        float* Wo = (float*)sp + 192;
        bn_coeffs(2, g3, be3, N, sc, sf);
        if (tid < 192) Wo[tid] = W4[tid];
        __syncthreads();
        int warp = tid >> 5, lane = tid & 31;
        for (int row = bid * 8 + warp; row < N; row += nb * 8) {
            float s0 = 0.f, s1 = 0.f;
            #pragma unroll
            for (int k0 = 0; k0 < 96; k0 += 32) {
                int c = k0 + lane;
                float xv = g_bufB[(size_t)row * 96 + c];
                xv = fmaxf(fmaf(xv, sc[c], sf[c]), 0.f);
                s0 += xv * Wo[c * 2];
                s1 += xv * Wo[c * 2 + 1];
            }
            #pragma unroll
            for (int o = 16; o; o >>= 1) {
                s0 += __shfl_down_sync(0xffffffffu, s0, o);
                s1 += __shfl_down_sync(0xffffffffu, s1, o);
            }
            if (lane == 0) {
                g_bufA[(size_t)row * 2]     = s0;
                g_bufA[(size_t)row * 2 + 1] = s1;
            }
        }
    }
    gsync(nb);

    // ---- final width-2 aggregation ----
    {
        int warp = tid >> 5, lane = tid & 31;
        float bb0 = b4[0], bb1 = b4[1];
        for (int gw = bid * 8 + warp; gw < N; gw += nb * 8) {
            int beg = g_offs[gw], end = g_offs[gw + 1];
            float a0 = 0.f, a1 = 0.f;
            for (int e = beg + lane; e < end; e += 32) {
                int2 ed = g_csr[e];
                float2 v = __ldg((const float2*)g_bufA + ed.x);
                float nm = __int_as_float(ed.y);
                a0 = fmaf(nm, v.x, a0);
                a1 = fmaf(nm, v.y, a1);
            }
            #pragma unroll
            for (int o = 16; o; o >>= 1) {
                a0 += __shfl_down_sync(0xffffffffu, a0, o);
                a1 += __shfl_down_sync(0xffffffffu, a1, o);
            }
            if (lane == 0) {
                float2 t = ((const float2*)g_bufA)[gw];
                float w = g_dinv2[gw];
                out[2 * gw]     = bb0 + t.x * w + a0;
                out[2 * gw + 1] = bb1 + t.y * w + a1;
            }
        }
    }
}

// ---------------- host ----------------
extern "C" void kernel_launch(void* const* d_in, const int* in_sizes, int n_in,
                              void* d_out, int out_size) {
    const float* x  = (const float*)d_in[0];
    const int*   ei = (const int*)d_in[1];
    const float* W1 = (const float*)d_in[2];  const float* b1 = (const float*)d_in[3];
    const float* g1 = (const float*)d_in[4];  const float* be1 = (const float*)d_in[5];
    const float* W2 = (const float*)d_in[6];  const float* b2 = (const float*)d_in[7];
    const float* g2 = (const float*)d_in[8];  const float* be2 = (const float*)d_in[9];
    const float* W3 = (const float*)d_in[10]; const float* b3 = (const float*)d_in[11];
    const float* g3 = (const float*)d_in[12]; const float* be3 = (const float*)d_in[13];
    const float* W4 = (const float*)d_in[14]; const float* b4 = (const float*)d_in[15];
    float* out = (float*)d_out;

    int E   = in_sizes[1] / 2;
    int H   = in_sizes[3];           // 96
    int Fin = in_sizes[2] / H;       // 32
    int N   = in_sizes[0] / Fin;     // 50000
    (void)n_in; (void)out_size;

    int dev = 0;
    cudaGetDevice(&dev);
    int nsm = 0;
    cudaDeviceGetAttribute(&nsm, cudaDevAttrMultiProcessorCount, dev);
    int bpm = 0;
    cudaOccupancyMaxActiveBlocksPerMultiprocessor(&bpm, k_mega, 256, 0);
    if (bpm < 1) bpm = 1;
    int nb = nsm * bpm;
    if (nb < 1) nb = 148;

    k_mega<<<nb, 256>>>(x, ei, W1, b1, g1, be1, W2, b2, g2, be2,
                        W3, b3, g3, be3, W4, b4, out, N, E, Fin, nb);
}

// round 7
// speedup vs baseline: 1.0721x; 1.0721x over previous
#include <cuda_runtime.h>
#include <cstdint>

// ---------------- static device scratch ----------------
#define MAXN 131072
#define MAXE 2000000

__device__ int    g_deg[MAXN];          // self-cleaning: zeroed at end of k_offsets
__device__ float  g_dinv[MAXN];
__device__ float  g_dinv2[MAXN];
__device__ int    g_offs[MAXN + 1];
__device__ int    g_cursor[MAXN];
__device__ int    g_bsum[MAXN / 256 + 2];
__device__ int2   g_csr[MAXE];          // (src, norm-as-int)
__device__ float  g_bufA[(size_t)MAXN * 96];
__device__ float  g_bufB[(size_t)MAXN * 96];
__device__ double g_sumS[3][8][96];     // per-layer BN stat shadows (zeroed by preceding agg)
__device__ double g_sqS[3][8][96];
__device__ float  g_scale[96];          // layer-3 coeffs for gemm_out
__device__ float  g_shift[96];

// ---------------- per-block edge dtype detection ----------------
// int64 edges: high 32-bit words of the first 256 values are all zero.
__device__ __forceinline__ int detect_is64(const int* __restrict__ p) {
    __shared__ int s64;
    if (threadIdx.x == 0) s64 = 1;
    __syncthreads();
    if (threadIdx.x < 256) {
        if (p[2 * threadIdx.x + 1] != 0) s64 = 0;   // benign race
    }
    __syncthreads();
    return s64;
}

// ---------------- preprocessing ----------------
__global__ void k_count(const int* __restrict__ p, int E) {
    int is64 = detect_is64(p);
    int e = blockIdx.x * blockDim.x + threadIdx.x;
    if (e >= E) return;
    int d = is64 ? p[2 * (E + e)] : p[E + e];
    atomicAdd(&g_deg[d], 1);
}

__global__ void k_dinv_bsum(int N) {
    __shared__ int sh[256];
    int t = threadIdx.x;
    int i = blockIdx.x * 256 + t;
    int dg = (i < N) ? g_deg[i] : 0;
    if (i < N) {
        float dt = (float)(dg + 1);   // +1 self-loop
        g_dinv[i]  = rsqrtf(dt);
        g_dinv2[i] = 1.0f / dt;
    }
    sh[t] = dg;
    __syncthreads();
    for (int s = 128; s; s >>= 1) {
        if (t < s) sh[t] += sh[t + s];
        __syncthreads();
    }
    if (t == 0) g_bsum[blockIdx.x] = sh[0];
}

// offsets with inlined cross-block prefix; zeroes g_deg after last use
__global__ void k_offsets(int N) {
    __shared__ int sh[256];
    __shared__ int red[256];
    int t = threadIdx.x;
    int acc = 0;
    for (int i = t; i < blockIdx.x; i += 256) acc += g_bsum[i];
    red[t] = acc;
    __syncthreads();
    for (int s = 128; s; s >>= 1) {
        if (t < s) red[t] += red[t + s];
        __syncthreads();
    }
    int bpre = red[0];

    int i = blockIdx.x * 256 + t;
    int v = (i < N) ? g_deg[i] : 0;
    sh[t] = v;
    __syncthreads();
    for (int o = 1; o < 256; o <<= 1) {
        int x = (t >= o) ? sh[t - o] : 0;
        __syncthreads();
        sh[t] += x;
        __syncthreads();
    }
    if (i < N) {
        int off = bpre + sh[t] - v;
        g_offs[i]   = off;
        g_cursor[i] = off;
        if (i == N - 1) g_offs[N] = off + v;
        g_deg[i] = 0;               // self-clean for next graph replay
    }
}

__global__ void k_scatter(const int* __restrict__ p, int E) {
    int is64 = detect_is64(p);
    int e = blockIdx.x * blockDim.x + threadIdx.x;
    if (e >= E) return;
    int s, d;
    if (is64) { s = p[2 * e]; d = p[2 * (E + e)]; }
    else      { s = p[e];     d = p[E + e]; }
    int pos = atomicAdd(&g_cursor[d], 1);
    g_csr[pos] = make_int2(s, __float_as_int(g_dinv[s] * g_dinv[d]));
}

// ---------------- CSR gather (warp per node), 4x edge unroll ----------------
// NL float4 lanes active. ZL >= 0: block 0 zeroes stat shadows for layer ZL.
template<int NL, int ZL>
__global__ __launch_bounds__(256) void k_agg(
    const float* __restrict__ h, float* __restrict__ out, int N) {
    if (ZL >= 0 && blockIdx.x == 0) {
        for (int i = threadIdx.x; i < 768; i += 256) {
            ((double*)g_sumS[ZL])[i] = 0.0;
            ((double*)g_sqS[ZL])[i]  = 0.0;
        }
    }
    int gw   = (blockIdx.x * blockDim.x + threadIdx.x) >> 5;
    int lane = threadIdx.x & 31;
    if (gw >= N) return;
    const float4* hp = (const float4*)h;
    bool act = lane < NL;
    float4 acc = make_float4(0, 0, 0, 0);
    if (act) {
        float4 v = __ldg(hp + (size_t)gw * NL + lane);
        float w = g_dinv2[gw];
        acc = make_float4(v.x * w, v.y * w, v.z * w, v.w * w);
    }
    int beg = g_offs[gw], end = g_offs[gw + 1];
    for (int e0 = beg; e0 < end; e0 += 32) {
        int e = e0 + lane;
        int2 ed = (e < end) ? g_csr[e] : make_int2(0, 0);
        int m = end - e0; if (m > 32) m = 32;
        int j = 0;
        for (; j + 4 <= m; j += 4) {
            int   s0 = __shfl_sync(0xffffffffu, ed.x, j);
            float n0 = __int_as_float(__shfl_sync(0xffffffffu, ed.y, j));
            int   s1 = __shfl_sync(0xffffffffu, ed.x, j + 1);
            float n1 = __int_as_float(__shfl_sync(0xffffffffu, ed.y, j + 1));
            int   s2 = __shfl_sync(0xffffffffu, ed.x, j + 2);
            float n2 = __int_as_float(__shfl_sync(0xffffffffu, ed.y, j + 2));
            int   s3 = __shfl_sync(0xffffffffu, ed.x, j + 3);
            float n3 = __int_as_float(__shfl_sync(0xffffffffu, ed.y, j + 3));
            if (act) {
                float4 v0 = __ldg(hp + (size_t)s0 * NL + lane);
                float4 v1 = __ldg(hp + (size_t)s1 * NL + lane);
                float4 v2 = __ldg(hp + (size_t)s2 * NL + lane);
                float4 v3 = __ldg(hp + (size_t)s3 * NL + lane);
                acc.x = fmaf(n0, v0.x, acc.x); acc.y = fmaf(n0, v0.y, acc.y);
                acc.z = fmaf(n0, v0.z, acc.z); acc.w = fmaf(n0, v0.w, acc.w);
                acc.x = fmaf(n1, v1.x, acc.x); acc.y = fmaf(n1, v1.y, acc.y);
                acc.z = fmaf(n1, v1.z, acc.z); acc.w = fmaf(n1, v1.w, acc.w);
                acc.x = fmaf(n2, v2.x, acc.x); acc.y = fmaf(n2, v2.y, acc.y);
                acc.z = fmaf(n2, v2.z, acc.z); acc.w = fmaf(n2, v2.w, acc.w);
                acc.x = fmaf(n3, v3.x, acc.x); acc.y = fmaf(n3, v3.y, acc.y);
                acc.z = fmaf(n3, v3.z, acc.z); acc.w = fmaf(n3, v3.w, acc.w);
            }
        }
        for (; j < m; j++) {
            int   s0 = __shfl_sync(0xffffffffu, ed.x, j);
            float n0 = __int_as_float(__shfl_sync(0xffffffffu, ed.y, j));
            if (act) {
                float4 v0 = __ldg(hp + (size_t)s0 * NL + lane);
                acc.x = fmaf(n0, v0.x, acc.x); acc.y = fmaf(n0, v0.y, acc.y);
                acc.z = fmaf(n0, v0.z, acc.z); acc.w = fmaf(n0, v0.w, acc.w);
            }
        }
    }
    if (act) ((float4*)out)[(size_t)gw * NL + lane] = acc;
}

// ---------------- GEMM: Y[N,96] = X[N,Fi] @ W[Fi,96] + b, FFMA2, fused BN stats ----------------
__global__ __launch_bounds__(256) void k_gemm96(
    const float* __restrict__ X, const float* __restrict__ W,
    const float* __restrict__ b, float* __restrict__ Y,
    int N, int Fi, int layer) {
    __shared__ float Ws[96 * 96];
    __shared__ float Xt[96 * 32];
    int tid = threadIdx.x;
    int tx = tid & 15, ty = tid >> 4;
    for (int i = tid; i < Fi * 96; i += 256) Ws[i] = W[i];
    int row0 = blockIdx.x * 32;
    for (int i = tid; i < 32 * Fi; i += 256) {
        int r = i & 31, k = i >> 5;
        int row = row0 + r;
        Xt[k * 32 + r] = (row < N) ? X[(size_t)row * Fi + k] : 0.0f;
    }
    __syncthreads();

    unsigned long long acc[2][3] = {{0, 0, 0}, {0, 0, 0}};
    int cb = ty * 6;
    #pragma unroll 4
    for (int k = 0; k < Fi; k++) {
        float2 a2 = *(const float2*)&Xt[k * 32 + 2 * tx];
        unsigned long long p0, p1;
        asm("mov.b64 %0, {%1, %1};" : "=l"(p0) : "f"(a2.x));
        asm("mov.b64 %0, {%1, %1};" : "=l"(p1) : "f"(a2.y));
        const unsigned long long* wrow = (const unsigned long long*)&Ws[k * 96 + cb];
        #pragma unroll
        for (int p = 0; p < 3; p++) {
            unsigned long long w2 = wrow[p];
            asm("fma.rn.f32x2 %0, %1, %2, %0;" : "+l"(acc[0][p]) : "l"(p0), "l"(w2));
            asm("fma.rn.f32x2 %0, %1, %2, %0;" : "+l"(acc[1][p]) : "l"(p1), "l"(w2));
        }
    }

    float bb[6];
    #pragma unroll
    for (int j = 0; j < 6; j++) bb[j] = b[cb + j];
    float ls[6] = {0, 0, 0, 0, 0, 0}, lq[6] = {0, 0, 0, 0, 0, 0};
    #pragma unroll
    for (int rr = 0; rr < 2; rr++) {
        int row = row0 + 2 * tx + rr;
        if (row < N) {
            float v[6];
            #pragma unroll
            for (int p = 0; p < 3; p++)
                asm("mov.b64 {%0, %1}, %2;" : "=f"(v[2 * p]), "=f"(v[2 * p + 1]) : "l"(acc[rr][p]));
            #pragma unroll
            for (int j = 0; j < 6; j++) {
                float val = v[j] + bb[j];
                v[j] = val;
                ls[j] += val; lq[j] += val * val;
            }
            float2* yp = (float2*)&Y[(size_t)row * 96 + cb];
            yp[0] = make_float2(v[0], v[1]);
            yp[1] = make_float2(v[2], v[3]);
            yp[2] = make_float2(v[4], v[5]);
        }
    }

    __syncthreads();
    float* sr = Xt;
    int sh = blockIdx.x & 7;
    #pragma unroll
    for (int j = 0; j < 6; j++) sr[tx * 102 + cb + j] = ls[j];
    __syncthreads();
    for (int st = 8; st; st >>= 1) {
        if (tx < st)
            #pragma unroll
            for (int j = 0; j < 6; j++)
                sr[tx * 102 + cb + j] += sr[(tx + st) * 102 + cb + j];
        __syncthreads();
    }
    if (tx == 0)
        #pragma unroll
        for (int j = 0; j < 6; j++) atomicAdd(&g_sumS[layer][sh][cb + j], (double)sr[cb + j]);
    __syncthreads();
    #pragma unroll
    for (int j = 0; j < 6; j++) sr[tx * 102 + cb + j] = lq[j];
    __syncthreads();
    for (int st = 8; st; st >>= 1) {
        if (tx < st)
            #pragma unroll
            for (int j = 0; j < 6; j++)
                sr[tx * 102 + cb + j] += sr[(tx + st) * 102 + cb + j];
        __syncthreads();
    }
    if (tx == 0)
        #pragma unroll
        for (int j = 0; j < 6; j++) atomicAdd(&g_sqS[layer][sh][cb + j], (double)sr[cb + j]);
}

// BN+ReLU in place (fp32), coefficients computed per block from stat shadows
__global__ __launch_bounds__(256) void k_bnrelu(
    float* __restrict__ X,
    const float* __restrict__ g, const float* __restrict__ be, int N, int layer) {
    __shared__ float sc[96], sf[96];
    int t = threadIdx.x;
    if (t < 96) {
        double s = 0.0, q = 0.0;
        #pragma unroll
        for (int i = 0; i < 8; i++) { s += g_sumS[layer][i][t]; q += g_sqS[layer][i][t]; }
        double mu  = s / (double)N;
        double var = q / (double)N - mu * mu;
        if (var < 0.0) var = 0.0;
        float a = g[t] * rsqrtf((float)var + 1e-5f);
        sc[t] = a;
        sf[t] = be[t] - (float)mu * a;
    }
    __syncthreads();
    int total4 = N * 24;
    for (int i = blockIdx.x * 256 + t; i < total4; i += gridDim.x * 256) {
        int c = (i % 24) * 4;
        float4 v = ((const float4*)X)[i];
        v.x = fmaxf(fmaf(v.x, sc[c],     sf[c]),     0.f);
        v.y = fmaxf(fmaf(v.y, sc[c + 1], sf[c + 1]), 0.f);
        v.z = fmaxf(fmaf(v.z, sc[c + 2], sf[c + 2]), 0.f);
        v.w = fmaxf(fmaf(v.w, sc[c + 3], sf[c + 3]), 0.f);
        ((float4*)X)[i] = v;
    }
}

// layer-3 BN coeffs to global (consumed by gemm_out)
__global__ void k_bnfin(const float* __restrict__ g, const float* __restrict__ be, int N) {
    int c = threadIdx.x;
    if (c >= 96) return;
    double s = 0.0, q = 0.0;
    #pragma unroll
    for (int i = 0; i < 8; i++) { s += g_sumS[2][i][c]; q += g_sqS[2][i][c]; }
    double mu  = s / (double)N;
    double var = q / (double)N - mu * mu;
    if (var < 0.0) var = 0.0;
    float a = g[c] * rsqrtf((float)var + 1e-5f);
    g_scale[c] = a;
    g_shift[c] = be[c] - (float)mu * a;
}

// ---------------- final projection with fused BN3+ReLU: T[N,2] ----------------
__global__ __launch_bounds__(256) void k_gemm_out(
    const float* __restrict__ X, const float* __restrict__ W,
    float* __restrict__ T, int N) {
    __shared__ float Ws[192];
    int tid = threadIdx.x;
    if (tid < 192) Ws[tid] = W[tid];
    __syncthreads();
    int warp = tid / 32, lane = tid % 32;
    int row = blockIdx.x * 8 + warp;
    if (row >= N) return;
    float s0 = 0.0f, s1 = 0.0f;
    #pragma unroll
    for (int k0 = 0; k0 < 96; k0 += 32) {
        int c = k0 + lane;
        float x = X[(size_t)row * 96 + c];
        x = fmaxf(fmaf(x, g_scale[c], g_shift[c]), 0.f);
        s0 += x * Ws[c * 2];
        s1 += x * Ws[c * 2 + 1];
    }
    #pragma unroll
    for (int o = 16; o; o >>= 1) {
        s0 += __shfl_down_sync(0xffffffffu, s0, o);
        s1 += __shfl_down_sync(0xffffffffu, s1, o);
    }
    if (lane == 0) { T[(size_t)row * 2] = s0; T[(size_t)row * 2 + 1] = s1; }
}

// final width-2 aggregation: out[i] = b4 + T[i]*dinv2[i] + sum_e norm*T[src]
__global__ __launch_bounds__(256) void k_aggf(
    const float* __restrict__ T, const float* __restrict__ b4,
    float* __restrict__ out, int N) {
    int gw   = (blockIdx.x * blockDim.x + threadIdx.x) >> 5;
    int lane = threadIdx.x & 31;
    if (gw >= N) return;
    int beg = g_offs[gw], end = g_offs[gw + 1];
    float a0 = 0.f, a1 = 0.f;
    for (int e = beg + lane; e < end; e += 32) {
        int2 ed = g_csr[e];
        float2 v = __ldg((const float2*)T + ed.x);
        float nm = __int_as_float(ed.y);
        a0 = fmaf(nm, v.x, a0);
        a1 = fmaf(nm, v.y, a1);
    }
    #pragma unroll
    for (int o = 16; o; o >>= 1) {
        a0 += __shfl_down_sync(0xffffffffu, a0, o);
        a1 += __shfl_down_sync(0xffffffffu, a1, o);
    }
    if (lane == 0) {
        float2 t = ((const float2*)T)[gw];
        float w = g_dinv2[gw];
        out[2 * gw]     = b4[0] + t.x * w + a0;
        out[2 * gw + 1] = b4[1] + t.y * w + a1;
    }
}

// ---------------- host ----------------
static inline int cdiv(int a, int b) { return (a + b - 1) / b; }

extern "C" void kernel_launch(void* const* d_in, const int* in_sizes, int n_in,
                              void* d_out, int out_size) {
    const float* x  = (const float*)d_in[0];
    const int*   ei = (const int*)d_in[1];
    const float* W1 = (const float*)d_in[2];  const float* b1 = (const float*)d_in[3];
    const float* g1 = (const float*)d_in[4];  const float* be1 = (const float*)d_in[5];
    const float* W2 = (const float*)d_in[6];  const float* b2 = (const float*)d_in[7];
    const float* g2 = (const float*)d_in[8];  const float* be2 = (const float*)d_in[9];
    const float* W3 = (const float*)d_in[10]; const float* b3 = (const float*)d_in[11];
    const float* g3 = (const float*)d_in[12]; const float* be3 = (const float*)d_in[13];
    const float* W4 = (const float*)d_in[14]; const float* b4 = (const float*)d_in[15];
    float* out = (float*)d_out;

    int E   = in_sizes[1] / 2;
    int H   = in_sizes[3];           // 96
    int Fin = in_sizes[2] / H;       // 32
    int N   = in_sizes[0] / Fin;     // 50000
    (void)n_in; (void)out_size;

    void *pA = nullptr, *pB = nullptr;
    cudaGetSymbolAddress(&pA, g_bufA);
    cudaGetSymbolAddress(&pB, g_bufB);
    float* bufA = (float*)pA;
    float* bufB = (float*)pB;

    int nb = cdiv(N, 256);
    int gemmGrid = cdiv(N, 32);
    int aggGrid  = cdiv(N, 8);

    // -------- per-call graph preprocessing (g_deg self-cleans each call) --------
    k_count    <<<cdiv(E, 256), 256>>>(ei, E);
    k_dinv_bsum<<<nb, 256>>>(N);
    k_offsets  <<<nb, 256>>>(N);
    k_scatter  <<<cdiv(E, 256), 256>>>(ei, E);

    // -------- layer 1 --------
    k_agg<8, 0><<<aggGrid, 256>>>(x, bufA, N);                    // zeroes stats[0]
    k_gemm96<<<gemmGrid, 256>>>(bufA, W1, b1, bufB, N, Fin, 0);
    k_bnrelu<<<1024, 256>>>(bufB, g1, be1, N, 0);

    // -------- layer 2 --------
    k_agg<24, 1><<<aggGrid, 256>>>(bufB, bufA, N);                // zeroes stats[1]
    k_gemm96<<<gemmGrid, 256>>>(bufA, W2, b2, bufB, N, 96, 1);
    k_bnrelu<<<1024, 256>>>(bufB, g2, be2, N, 1);

    // -------- layer 3 --------
    k_agg<24, 2><<<aggGrid, 256>>>(bufB, bufA, N);                // zeroes stats[2]
    k_gemm96<<<gemmGrid, 256>>>(bufA, W3, b3, bufB, N, 96, 2);
    k_bnfin<<<1, 96>>>(g3, be3, N);

    // -------- layer 4 --------
    k_gemm_out<<<cdiv(N, 8), 256>>>(bufB, W4, bufA, N);
    k_aggf<<<aggGrid, 256>>>(bufA, b4, out, N);
}

// round 8
// speedup vs baseline: 1.0765x; 1.0041x over previous
#include <cuda_runtime.h>
#include <cstdint>

// ---------------- static device scratch ----------------
#define MAXN 131072
#define MAXE 2000000

__device__ int    g_detect;             // 1 => int32 edges, 0 => int64
__device__ int    g_deg[MAXN];          // self-cleaning (zeroed in P3 after use)
__device__ float  g_dinv[MAXN];
__device__ float  g_dinv2[MAXN];
__device__ int    g_offs[MAXN + 1];
__device__ int    g_cursor[MAXN];
__device__ int    g_bsum[MAXN / 256 + 2];
__device__ int2   g_csr[MAXE];          // (src, norm-as-int)
__device__ float  g_bufA[(size_t)MAXN * 96];
__device__ float  g_bufB[(size_t)MAXN * 96];
__device__ double g_sumS[3][8][96];     // per-layer BN stat shadows
__device__ double g_sqS[3][8][96];
__device__ float  g_scaleL[3][96];      // per-layer BN coeffs (filled by gemm last block)
__device__ float  g_shiftL[3][96];
__device__ unsigned g_doneG;            // gemm block-completion counter (self-resetting)

// ---------------- grid barrier (for k_pre only) ----------------
__device__ unsigned g_cnt;
__device__ volatile unsigned g_gen;

__device__ __forceinline__ void gsync(int nb) {
    __syncthreads();
    if (threadIdx.x == 0) {
        __threadfence();
        unsigned gen = g_gen;
        if (atomicAdd(&g_cnt, 1u) == (unsigned)(nb - 1)) {
            atomicExch(&g_cnt, 0u);
            __threadfence();
            g_gen = gen + 1;
        } else {
            while (g_gen == gen) __nanosleep(64);
        }
        __threadfence();
    }
    __syncthreads();
}

// ---------------- persistent preprocessing kernel ----------------
// P0 detect + zero stats | P1 count | P2 dinv+chunk sums | P3 offsets(+zero deg) | P4 scatter
__global__ __launch_bounds__(256) void k_pre(const int* __restrict__ ei,
                                             int N, int E, int nb) {
    __shared__ int ish[256];
    __shared__ int red[256];
    int tid = threadIdx.x;
    int bid = blockIdx.x;

    // ---- P0 ----
    for (int i = bid * 256 + tid; i < 2304; i += nb * 256) {
        ((double*)g_sumS)[i] = 0.0;
        ((double*)g_sqS)[i]  = 0.0;
    }
    if (bid == 0) {
        if (tid == 0) g_detect = 0;
        __syncthreads();
        if (ei[2 * tid + 1] != 0) g_detect = 1;   // benign race: int32 if any high word nonzero
    }
    gsync(nb);
    int is64 = (g_detect == 0);

    // ---- P1: degree count ----
    for (int e = bid * 256 + tid; e < E; e += nb * 256) {
        int d = is64 ? ei[2 * (E + e)] : ei[E + e];
        atomicAdd(&g_deg[d], 1);
    }
    gsync(nb);

    // ---- P2: dinv + per-chunk degree sums ----
    int nch = (N + 255) >> 8;
    for (int c = bid; c < nch; c += nb) {
        int i = c * 256 + tid;
        int dg = (i < N) ? g_deg[i] : 0;
        if (i < N) {
            float dt = (float)(dg + 1);   // +1 self-loop
            g_dinv[i]  = rsqrtf(dt);
            g_dinv2[i] = 1.0f / dt;
        }
        __syncthreads();
        ish[tid] = dg;
        __syncthreads();
        for (int s = 128; s; s >>= 1) { if (tid < s) ish[tid] += ish[tid + s]; __syncthreads(); }
        if (tid == 0) g_bsum[c] = ish[0];
        __syncthreads();
    }
    gsync(nb);

    // ---- P3: offsets (chunk scan + cross-chunk prefix), zero deg after ----
    for (int c = bid; c < nch; c += nb) {
        int acc = 0;
        for (int i = tid; i < c; i += 256) acc += g_bsum[i];
        __syncthreads();
        red[tid] = acc;
        __syncthreads();
        for (int s = 128; s; s >>= 1) { if (tid < s) red[tid] += red[tid + s]; __syncthreads(); }
        int bpre = red[0];
        int i = c * 256 + tid;
        int v = (i < N) ? g_deg[i] : 0;
        __syncthreads();
        ish[tid] = v;
        __syncthreads();
        for (int o = 1; o < 256; o <<= 1) {
            int xv = (tid >= o) ? ish[tid - o] : 0;
            __syncthreads();
            ish[tid] += xv;
            __syncthreads();
        }
        if (i < N) {
            int off = bpre + ish[tid] - v;
            g_offs[i]   = off;
            g_cursor[i] = off;
            if (i == N - 1) g_offs[N] = off + v;
            g_deg[i] = 0;             // self-clean for next call
        }
        __syncthreads();
    }
    gsync(nb);

    // ---- P4: scatter edges into CSR ----
    for (int e = bid * 256 + tid; e < E; e += nb * 256) {
        int s, d;
        if (is64) { s = ei[2 * e]; d = ei[2 * (E + e)]; }
        else      { s = ei[e];     d = ei[E + e]; }
        int pos = atomicAdd(&g_cursor[d], 1);
        g_csr[pos] = make_int2(s, __float_as_int(g_dinv[s] * g_dinv[d]));
    }
}

// ---------------- CSR gather (warp per node), 2x edge unroll (R3-proven) ----------------
template<int NL>
__global__ __launch_bounds__(256) void k_agg(
    const float* __restrict__ h, float* __restrict__ out, int N) {
    int gw   = (blockIdx.x * blockDim.x + threadIdx.x) >> 5;
    int lane = threadIdx.x & 31;
    if (gw >= N) return;
    const float4* hp = (const float4*)h;
    bool act = lane < NL;
    float4 acc = make_float4(0, 0, 0, 0);
    if (act) {
        float4 v = __ldg(hp + (size_t)gw * NL + lane);
        float w = g_dinv2[gw];
        acc = make_float4(v.x * w, v.y * w, v.z * w, v.w * w);
    }
    int beg = g_offs[gw], end = g_offs[gw + 1];
    for (int e0 = beg; e0 < end; e0 += 32) {
        int e = e0 + lane;
        int2 ed = (e < end) ? g_csr[e] : make_int2(0, 0);
        int m = end - e0; if (m > 32) m = 32;
        int j = 0;
        for (; j + 2 <= m; j += 2) {
            int   s0 = __shfl_sync(0xffffffffu, ed.x, j);
            float n0 = __int_as_float(__shfl_sync(0xffffffffu, ed.y, j));
            int   s1 = __shfl_sync(0xffffffffu, ed.x, j + 1);
            float n1 = __int_as_float(__shfl_sync(0xffffffffu, ed.y, j + 1));
            if (act) {
                float4 v0 = __ldg(hp + (size_t)s0 * NL + lane);
                float4 v1 = __ldg(hp + (size_t)s1 * NL + lane);
                acc.x = fmaf(n0, v0.x, acc.x); acc.y = fmaf(n0, v0.y, acc.y);
                acc.z = fmaf(n0, v0.z, acc.z); acc.w = fmaf(n0, v0.w, acc.w);
                acc.x = fmaf(n1, v1.x, acc.x); acc.y = fmaf(n1, v1.y, acc.y);
                acc.z = fmaf(n1, v1.z, acc.z); acc.w = fmaf(n1, v1.w, acc.w);
            }
        }
        if (j < m) {
            int   s0 = __shfl_sync(0xffffffffu, ed.x, j);
            float n0 = __int_as_float(__shfl_sync(0xffffffffu, ed.y, j));
            if (act) {
                float4 v0 = __ldg(hp + (size_t)s0 * NL + lane);
                acc.x = fmaf(n0, v0.x, acc.x); acc.y = fmaf(n0, v0.y, acc.y);
                acc.z = fmaf(n0, v0.z, acc.z); acc.w = fmaf(n0, v0.w, acc.w);
            }
        }
    }
    if (act) ((float4*)out)[(size_t)gw * NL + lane] = acc;
}

// ---------------- GEMM: Y[N,96] = X[N,Fi] @ W[Fi,96] + b, FFMA2, fused BN stats ----------------
// Last-finishing block computes BN coefficients for this layer.
__global__ __launch_bounds__(256) void k_gemm96(
    const float* __restrict__ X, const float* __restrict__ W,
    const float* __restrict__ b, float* __restrict__ Y,
    const float* __restrict__ g, const float* __restrict__ be,
    int N, int Fi, int layer) {
    __shared__ float Ws[96 * 96];
    __shared__ float Xt[96 * 32];
    __shared__ unsigned rank_s;
    int tid = threadIdx.x;
    int tx = tid & 15, ty = tid >> 4;
    for (int i = tid; i < Fi * 96; i += 256) Ws[i] = W[i];
    int row0 = blockIdx.x * 32;
    for (int i = tid; i < 32 * Fi; i += 256) {
        int r = i & 31, k = i >> 5;
        int row = row0 + r;
        Xt[k * 32 + r] = (row < N) ? X[(size_t)row * Fi + k] : 0.0f;
    }
    __syncthreads();

    unsigned long long acc[2][3] = {{0, 0, 0}, {0, 0, 0}};
    int cb = ty * 6;
    #pragma unroll 4
    for (int k = 0; k < Fi; k++) {
        float2 a2 = *(const float2*)&Xt[k * 32 + 2 * tx];
        unsigned long long p0, p1;
        asm("mov.b64 %0, {%1, %1};" : "=l"(p0) : "f"(a2.x));
        asm("mov.b64 %0, {%1, %1};" : "=l"(p1) : "f"(a2.y));
        const unsigned long long* wrow = (const unsigned long long*)&Ws[k * 96 + cb];
        #pragma unroll
        for (int p = 0; p < 3; p++) {
            unsigned long long w2 = wrow[p];
            asm("fma.rn.f32x2 %0, %1, %2, %0;" : "+l"(acc[0][p]) : "l"(p0), "l"(w2));
            asm("fma.rn.f32x2 %0, %1, %2, %0;" : "+l"(acc[1][p]) : "l"(p1), "l"(w2));
        }
    }

    float bb[6];
    #pragma unroll
    for (int j = 0; j < 6; j++) bb[j] = b[cb + j];
    float ls[6] = {0, 0, 0, 0, 0, 0}, lq[6] = {0, 0, 0, 0, 0, 0};
    #pragma unroll
    for (int rr = 0; rr < 2; rr++) {
        int row = row0 + 2 * tx + rr;
        if (row < N) {
            float v[6];
            #pragma unroll
            for (int p = 0; p < 3; p++)
                asm("mov.b64 {%0, %1}, %2;" : "=f"(v[2 * p]), "=f"(v[2 * p + 1]) : "l"(acc[rr][p]));
            #pragma unroll
            for (int j = 0; j < 6; j++) {
                float val = v[j] + bb[j];
                v[j] = val;
                ls[j] += val; lq[j] += val * val;
            }
            float2* yp = (float2*)&Y[(size_t)row * 96 + cb];
            yp[0] = make_float2(v[0], v[1]);
            yp[1] = make_float2(v[2], v[3]);
            yp[2] = make_float2(v[4], v[5]);
        }
    }

    // block stats reduction (Xt reused; pad 102 to dodge conflicts)
    __syncthreads();
    float* sr = Xt;
    int sh = blockIdx.x & 7;
    #pragma unroll
    for (int j = 0; j < 6; j++) sr[tx * 102 + cb + j] = ls[j];
    __syncthreads();
    for (int st = 8; st; st >>= 1) {
        if (tx < st)
            #pragma unroll
            for (int j = 0; j < 6; j++)
                sr[tx * 102 + cb + j] += sr[(tx + st) * 102 + cb + j];
        __syncthreads();
    }
    if (tx == 0)
        #pragma unroll
        for (int j = 0; j < 6; j++) atomicAdd(&g_sumS[layer][sh][cb + j], (double)sr[cb + j]);
    __syncthreads();
    #pragma unroll
    for (int j = 0; j < 6; j++) sr[tx * 102 + cb + j] = lq[j];
    __syncthreads();
    for (int st = 8; st; st >>= 1) {
        if (tx < st)
            #pragma unroll
            for (int j = 0; j < 6; j++)
                sr[tx * 102 + cb + j] += sr[(tx + st) * 102 + cb + j];
        __syncthreads();
    }
    if (tx == 0)
        #pragma unroll
        for (int j = 0; j < 6; j++) atomicAdd(&g_sqS[layer][sh][cb + j], (double)sr[cb + j]);

    // last-finishing block computes BN coefficients for this layer
    __threadfence();
    __syncthreads();
    if (tid == 0) rank_s = atomicAdd(&g_doneG, 1u);
    __syncthreads();
    if (rank_s == gridDim.x - 1) {
        __threadfence();
        if (tid < 96) {
            double s = 0.0, q = 0.0;
            #pragma unroll
            for (int i = 0; i < 8; i++) { s += g_sumS[layer][i][tid]; q += g_sqS[layer][i][tid]; }
            double mu  = s / (double)N;
            double var = q / (double)N - mu * mu;
            if (var < 0.0) var = 0.0;
            float a = g[tid] * rsqrtf((float)var + 1e-5f);
            g_scaleL[layer][tid] = a;
            g_shiftL[layer][tid] = be[tid] - (float)mu * a;
        }
        if (tid == 0) atomicExch(&g_doneG, 0u);   // reset for next gemm launch
    }
}

// elementwise BN+ReLU in place (fp32), coeffs precomputed by gemm's last block
__global__ __launch_bounds__(256) void k_bnrelu(float* __restrict__ X, int N, int layer) {
    __shared__ float sc[96], sf[96];
    int t = threadIdx.x;
    if (t < 96) { sc[t] = g_scaleL[layer][t]; sf[t] = g_shiftL[layer][t]; }
    __syncthreads();
    int total4 = N * 24;
    for (int i = blockIdx.x * 256 + t; i < total4; i += gridDim.x * 256) {
        int c = (i % 24) * 4;
        float4 v = ((const float4*)X)[i];
        v.x = fmaxf(fmaf(v.x, sc[c],     sf[c]),     0.f);
        v.y = fmaxf(fmaf(v.y, sc[c + 1], sf[c + 1]), 0.f);
        v.z = fmaxf(fmaf(v.z, sc[c + 2], sf[c + 2]), 0.f);
        v.w = fmaxf(fmaf(v.w, sc[c + 3], sf[c + 3]), 0.f);
        ((float4*)X)[i] = v;
    }
}

// ---------------- final projection with fused BN3+ReLU: T[N,2] ----------------
__global__ __launch_bounds__(256) void k_gemm_out(
    const float* __restrict__ X, const float* __restrict__ W,
    float* __restrict__ T, int N) {
    __shared__ float Ws[192];
    __shared__ float sc[96], sf[96];
    int tid = threadIdx.x;
    if (tid < 192) Ws[tid] = W[tid];
    if (tid < 96) { sc[tid] = g_scaleL[2][tid]; sf[tid] = g_shiftL[2][tid]; }
    __syncthreads();
    int warp = tid / 32, lane = tid % 32;
    int row = blockIdx.x * 8 + warp;
    if (row >= N) return;
    float s0 = 0.0f, s1 = 0.0f;
    #pragma unroll
    for (int k0 = 0; k0 < 96; k0 += 32) {
        int c = k0 + lane;
        float x = X[(size_t)row * 96 + c];
        x = fmaxf(fmaf(x, sc[c], sf[c]), 0.f);
        s0 += x * Ws[c * 2];
        s1 += x * Ws[c * 2 + 1];
    }
    #pragma unroll
    for (int o = 16; o; o >>= 1) {
        s0 += __shfl_down_sync(0xffffffffu, s0, o);
        s1 += __shfl_down_sync(0xffffffffu, s1, o);
    }
    if (lane == 0) { T[(size_t)row * 2] = s0; T[(size_t)row * 2 + 1] = s1; }
}

// final width-2 aggregation: out[i] = b4 + T[i]*dinv2[i] + sum_e norm*T[src]
__global__ __launch_bounds__(256) void k_aggf(
    const float* __restrict__ T, const float* __restrict__ b4,
    float* __restrict__ out, int N) {
    int gw   = (blockIdx.x * blockDim.x + threadIdx.x) >> 5;
    int lane = threadIdx.x & 31;
    if (gw >= N) return;
    int beg = g_offs[gw], end = g_offs[gw + 1];
    float a0 = 0.f, a1 = 0.f;
    for (int e = beg + lane; e < end; e += 32) {
        int2 ed = g_csr[e];
        float2 v = __ldg((const float2*)T + ed.x);
        float nm = __int_as_float(ed.y);
        a0 = fmaf(nm, v.x, a0);
        a1 = fmaf(nm, v.y, a1);
    }
    #pragma unroll
    for (int o = 16; o; o >>= 1) {
        a0 += __shfl_down_sync(0xffffffffu, a0, o);
        a1 += __shfl_down_sync(0xffffffffu, a1, o);
    }
    if (lane == 0) {
        float2 t = ((const float2*)T)[gw];
        float w = g_dinv2[gw];
        out[2 * gw]     = b4[0] + t.x * w + a0;
        out[2 * gw + 1] = b4[1] + t.y * w + a1;
    }
}

// ---------------- host ----------------
static inline int cdiv(int a, int b) { return (a + b - 1) / b; }

extern "C" void kernel_launch(void* const* d_in, const int* in_sizes, int n_in,
                              void* d_out, int out_size) {
    const float* x  = (const float*)d_in[0];
    const int*   ei = (const int*)d_in[1];
    const float* W1 = (const float*)d_in[2];  const float* b1 = (const float*)d_in[3];
    const float* g1 = (const float*)d_in[4];  const float* be1 = (const float*)d_in[5];
    const float* W2 = (const float*)d_in[6];  const float* b2 = (const float*)d_in[7];
    const float* g2 = (const float*)d_in[8];  const float* be2 = (const float*)d_in[9];
    const float* W3 = (const float*)d_in[10]; const float* b3 = (const float*)d_in[11];
    const float* g3 = (const float*)d_in[12]; const float* be3 = (const float*)d_in[13];
    const float* W4 = (const float*)d_in[14]; const float* b4 = (const float*)d_in[15];
    float* out = (float*)d_out;

    int E   = in_sizes[1] / 2;
    int H   = in_sizes[3];           // 96
    int Fin = in_sizes[2] / H;       // 32
    int N   = in_sizes[0] / Fin;     // 50000
    (void)n_in; (void)out_size;

    void *pA = nullptr, *pB = nullptr;
    cudaGetSymbolAddress(&pA, g_bufA);
    cudaGetSymbolAddress(&pB, g_bufB);
    float* bufA = (float*)pA;
    float* bufB = (float*)pB;

    int gemmGrid = cdiv(N, 32);
    int aggGrid  = cdiv(N, 8);

    // persistent preprocessing grid
    int dev = 0;
    cudaGetDevice(&dev);
    int nsm = 0;
    cudaDeviceGetAttribute(&nsm, cudaDevAttrMultiProcessorCount, dev);
    int bpm = 0;
    cudaOccupancyMaxActiveBlocksPerMultiprocessor(&bpm, k_pre, 256, 0);
    if (bpm < 1) bpm = 1;
    int nbp = nsm * bpm;
    if (nbp < 1) nbp = 148;

    // -------- preprocessing (1 launch, 4 grid barriers) --------
    k_pre<<<nbp, 256>>>(ei, N, E, nbp);

    // -------- layer 1 --------
    k_agg<8><<<aggGrid, 256>>>(x, bufA, N);
    k_gemm96<<<gemmGrid, 256>>>(bufA, W1, b1, bufB, g1, be1, N, Fin, 0);
    k_bnrelu<<<1024, 256>>>(bufB, N, 0);

    // -------- layer 2 --------
    k_agg<24><<<aggGrid, 256>>>(bufB, bufA, N);
    k_gemm96<<<gemmGrid, 256>>>(bufA, W2, b2, bufB, g2, be2, N, 96, 1);
    k_bnrelu<<<1024, 256>>>(bufB, N, 1);

    // -------- layer 3 --------
    k_agg<24><<<aggGrid, 256>>>(bufB, bufA, N);
    k_gemm96<<<gemmGrid, 256>>>(bufA, W3, b3, bufB, g3, be3, N, 96, 2);

    // -------- layer 4 --------
    k_gemm_out<<<cdiv(N, 8), 256>>>(bufB, W4, bufA, N);
    k_aggf<<<aggGrid, 256>>>(bufA, b4, out, N);
}